// round 14
// baseline (speedup 1.0000x reference)
#include <cuda_runtime.h>
#include <math.h>
#include <stdint.h>

#define BATCH 64
#define TT    2048
#define HH    128
#define DIN   108
#define LL    37

#define BG    4      // batches per cluster
#define CSZ   4      // CTAs per cluster
#define UPC   32     // hidden units per CTA
#define RING  4      // h0 ring depth

#define WREG  112    // k-range held in registers
#define WSMK  16     // k-range held in smem

#define ACC1_OFF 1
#define ACC3_OFF 65
#define ACT_OFF  129
#define PRED_OFF (129 + BATCH*HH)

// ---------------- device scratch (static; no runtime allocation) ----------------
__device__ __align__(16) float g_pre[2][TT][512][BATCH];   // x@Wih0^T + (bih0+bhh0)
__device__ __align__(16) float g_hf[2][HH][BATCH];

__device__ __forceinline__ float sigf(float x)    { return 1.0f / (1.0f + __expf(-x)); }
__device__ __forceinline__ float tanhfast(float x){ return 2.0f / (1.0f + __expf(-2.0f * x)) - 1.0f; }

__device__ __forceinline__ unsigned long long pack2(float x, float y) {
    unsigned long long r;
    asm("mov.b64 %0, {%1, %2};" : "=l"(r) : "f"(x), "f"(y));
    return r;
}
__device__ __forceinline__ void fma2(unsigned long long& acc, unsigned long long w2,
                                     unsigned long long v2) {
    asm("fma.rn.f32x2 %0, %1, %2, %0;" : "+l"(acc) : "l"(w2), "l"(v2));
}
// async remote store, tx-tracked on the destination CTA's barrier replica
__device__ __forceinline__ void st_async_f32(uint32_t saddr, uint32_t mbaddr,
                                             uint32_t rk, float v) {
    uint32_t ra, rb;
    asm volatile("mapa.shared::cluster.u32 %0, %1, %2;" : "=r"(ra) : "r"(saddr), "r"(rk));
    asm volatile("mapa.shared::cluster.u32 %0, %1, %2;" : "=r"(rb) : "r"(mbaddr), "r"(rk));
    asm volatile("st.async.shared::cluster.mbarrier::complete_tx::bytes.b32 [%0], %1, [%2];"
                 :: "r"(ra), "r"(__float_as_uint(v)), "r"(rb) : "memory");
}
// plain arrival on a barrier replica in CTA rank rk
__device__ __forceinline__ void mbar_arrive_rk(uint32_t mbaddr, uint32_t rk) {
    asm volatile(
        "{\n\t.reg .b32 ra;\n\t"
        "mapa.shared::cluster.u32 ra, %0, %1;\n\t"
        "mbarrier.arrive.release.cluster.shared::cluster.b64 _, [ra];\n\t}"
        :: "r"(mbaddr), "r"(rk) : "memory");
}
__device__ __forceinline__ void mbar_expect_tx(uint32_t mbaddr, uint32_t tx) {
    asm volatile("mbarrier.arrive.expect_tx.shared.b64 _, [%0], %1;"
                 :: "r"(mbaddr), "r"(tx) : "memory");
}
__device__ __forceinline__ void mbar_wait_parity(uint32_t mbaddr, uint32_t parity) {
    uint32_t done;
    asm volatile(
        "{\n\t.reg .pred p;\n\t"
        "mbarrier.try_wait.parity.acquire.cluster.shared::cta.b64 p, [%1], %2;\n\t"
        "selp.b32 %0, 1, 0, p;\n\t}"
        : "=r"(done) : "r"(mbaddr), "r"(parity) : "memory");
    if (!done) {
        asm volatile(
            "{\n\t.reg .pred p;\n\t"
            "WL_%=:\n\t"
            "mbarrier.try_wait.parity.acquire.cluster.shared::cta.b64 p, [%0], %1, 0x989680;\n\t"
            "@p bra.uni WD_%=;\n\t"
            "bra.uni WL_%=;\n\t"
            "WD_%=:\n\t}"
            :: "r"(mbaddr), "r"(parity) : "memory");
    }
}
#define CLUSTER_SYNC() do { \
    asm volatile("barrier.cluster.arrive.aligned;" ::: "memory"); \
    asm volatile("barrier.cluster.wait.aligned;"   ::: "memory"); \
} while (0)
#define BAR_SYNC(id, cnt) asm volatile("bar.sync %0, %1;" :: "r"(id), "r"(cnt) : "memory")

// ==================================================================
// Kernel 1: precompute gate inputs  pre[br][t][row][b]
// ==================================================================
#define GX_XS 0
#define GX_WS (DIN*68)
#define GX_BS (GX_WS + 64*113)
#define GEMM_SMEM_FLOATS (GX_BS + 64)

__global__ void __launch_bounds__(128)
pre_gemm_kernel(const float* __restrict__ xl, const float* __restrict__ xr,
                const float* __restrict__ xo,
                const int* __restrict__ isl, const int* __restrict__ isr,
                const float* __restrict__ Wl, const float* __restrict__ bil, const float* __restrict__ bhl,
                const float* __restrict__ Wr, const float* __restrict__ bir, const float* __restrict__ bhr)
{
    extern __shared__ float sg[];
    float* xs  = sg + GX_XS;
    float* Wsm = sg + GX_WS;
    float* bsm = sg + GX_BS;

    const int rb  = blockIdx.x;
    const int t   = blockIdx.y;
    const int br  = blockIdx.z;
    const int tid = threadIdx.x;

    const float* xh  = br ? xr  : xl;
    const int*   ish = br ? isr : isl;
    const float* W   = br ? Wr  : Wl;
    const float* bi  = br ? bir : bil;
    const float* bh  = br ? bhr : bhl;

    for (int i = tid; i < BATCH * DIN; i += 128) {
        int b = i / DIN, k = i - b * DIN;
        float v;
        if (k < 99) v = xh[(b * TT + t) * 99 + k] * ((ish[b] != 0) ? 1.0f : 0.0f);
        else        v = xo[(b * TT + t) * 9 + (k - 99)];
        xs[k * 68 + b] = v;
    }
    for (int i = tid; i < 64 * DIN; i += 128) {
        int lr = i / DIN, k = i - lr * DIN;
        Wsm[lr * 113 + k] = W[(rb * 64 + lr) * DIN + k];
    }
    if (tid < 64) bsm[tid] = bi[rb * 64 + tid] + bh[rb * 64 + tid];
    __syncthreads();

    const int rg = tid >> 4;
    const int b4 = (tid & 15) * 4;

    float4 acc[8];
    #pragma unroll
    for (int j = 0; j < 8; ++j) {
        float bb = bsm[rg * 8 + j];
        acc[j] = make_float4(bb, bb, bb, bb);
    }
    #pragma unroll 4
    for (int k = 0; k < DIN; ++k) {
        float4 xv = *(const float4*)&xs[k * 68 + b4];
        #pragma unroll
        for (int j = 0; j < 8; ++j) {
            float w = Wsm[(rg * 8 + j) * 113 + k];
            acc[j].x += w * xv.x; acc[j].y += w * xv.y;
            acc[j].z += w * xv.z; acc[j].w += w * xv.w;
        }
    }
    #pragma unroll
    for (int j = 0; j < 8; ++j) {
        int row = rb * 64 + rg * 8 + j;
        *(float4*)&g_pre[br][t][row][b4] = acc[j];
    }
}

// ==================================================================
// Kernel 2: DECOUPLED-LAYER cluster recurrence.
// G0 (threads 0-127): layer-0 loop, runs ahead, fills 4-deep h0 ring
//   (st.async tx 2048B per slot-fill; pure-count free barriers mbf0,
//    count 8 = 2 consumer groups x 4 CTAs, give backpressure).
// G1 (threads 128-383): layer-1 loop, paces the kernel; waits h0(s)
//   (usually already buffered) + its own 2-slot h2 exchange (R12 protocol).
// ==================================================================
#define WS_OFF   0                         // ws[3][WSMK][128]
#define B1_OFF   (WS_OFF + 3*WSMK*HH)      // 128
#define H0R_OFF  (B1_OFF + HH)             // RING x 128 x 4
#define H2_OFF   (H0R_OFF + RING*HH*BG)    // 2 x 128 x 4
#define G_OFF    (H2_OFF + 2*HH*BG)        // g[3][128][4]
#define MBH0_OFF (G_OFF + 3*HH*BG)         // 4 x u64
#define MBF0_OFF (MBH0_OFF + 8)            // 4 x u64
#define MBH2_OFF (MBF0_OFF + 8)            // 2 x u64
#define REC_SMEM_FLOATS (MBH2_OFF + 4)

__global__ void __launch_bounds__(384, 1) __cluster_dims__(CSZ, 1, 1)
lstm_recurrent_kernel(const float* __restrict__ Whh0_l, const float* __restrict__ Whh0_r,
                      const float* __restrict__ Wih1_l, const float* __restrict__ Whh1_l,
                      const float* __restrict__ bih1_l, const float* __restrict__ bhh1_l,
                      const float* __restrict__ Wih1_r, const float* __restrict__ Whh1_r,
                      const float* __restrict__ bih1_r, const float* __restrict__ bhh1_r,
                      const int* __restrict__ dur)
{
    extern __shared__ float sm[];
    float* wsAll = sm + WS_OFF;
    float* b1sm  = sm + B1_OFF;
    float* h0ring = sm + H0R_OFF;   // [slot(4)][unit(128)][b(4)]
    float* h2buf  = sm + H2_OFF;    // [slot(2)][unit(128)][b(4)]
    float* gall   = sm + G_OFF;     // [jid][row(128)][b(4)]

    const int tid = threadIdx.x;
    const int blk = blockIdx.x;
    const int cid = blk >> 2;
    const int br  = cid >> 4;
    const int bg0 = (cid & 15) * BG;

    uint32_t rank;
    asm("mov.u32 %0, %%cluster_ctarank;" : "=r"(rank));
    const int cu0 = (int)rank * UPC;

    const float* Whh0 = br ? Whh0_r : Whh0_l;
    const float* Wih1 = br ? Wih1_r : Wih1_l;
    const float* Whh1 = br ? Whh1_r : Whh1_l;
    const float* bi1  = br ? bih1_r : bih1_l;
    const float* bh1  = br ? bhh1_r : bhh1_l;

    const int jid = tid >> 7;            // 0=G0(Whh0), 1=G1a(Wih1), 2=G1b(Whh1)
    const int r   = tid & 127;
    const int grow = (r >> 5) * HH + cu0 + (r & 31);

    const float* mat = (jid == 0) ? Whh0 : ((jid == 1) ? Wih1 : Whh1);

    float wreg[WREG];
    #pragma unroll
    for (int k = 0; k < WREG; ++k) wreg[k] = mat[grow * HH + k];
    float* wsm = wsAll + jid * WSMK * HH;
    for (int kk = 0; kk < WSMK; ++kk) wsm[kk * HH + r] = mat[grow * HH + WREG + kk];

    if (tid < HH) {
        int gr = (tid >> 5) * HH + cu0 + (tid & 31);
        b1sm[tid] = bi1[gr] + bh1[gr];
    }
    for (int i = tid; i < RING * HH * BG; i += 384) h0ring[i] = 0.0f;
    for (int i = tid; i < 2 * HH * BG; i += 384) h2buf[i] = 0.0f;

    const uint32_t mbh0 = (uint32_t)__cvta_generic_to_shared(sm + MBH0_OFF);
    const uint32_t mbf0 = (uint32_t)__cvta_generic_to_shared(sm + MBF0_OFF);
    const uint32_t mbh2 = (uint32_t)__cvta_generic_to_shared(sm + MBH2_OFF);
    if (tid == 0) {
        #pragma unroll
        for (int i = 0; i < RING; ++i) {
            asm volatile("mbarrier.init.shared.b64 [%0], %1;" :: "r"(mbh0 + 8u*i), "r"(1) : "memory");
            mbar_expect_tx(mbh0 + 8u*i, 2048u);   // arm fills s=0..3
            asm volatile("mbarrier.init.shared.b64 [%0], %1;" :: "r"(mbf0 + 8u*i), "r"(8) : "memory");
        }
        asm volatile("mbarrier.init.shared.b64 [%0], %1;" :: "r"(mbh2), "r"(1) : "memory");
        asm volatile("mbarrier.init.shared.b64 [%0], %1;" :: "r"(mbh2 + 8u), "r"(1) : "memory");
        mbar_expect_tx(mbh2, 2048u);        // h2 step 0
        mbar_expect_tx(mbh2 + 8u, 2048u);   // h2 step 1
    }
    __syncthreads();
    CLUSTER_SYNC();   // barriers armed + zeros + weights visible before any traffic

    const uint32_t h0base = (uint32_t)__cvta_generic_to_shared(h0ring);
    const uint32_t h2base = (uint32_t)__cvta_generic_to_shared(h2buf);

    const int su = (tid & 127) >> 2;
    const int sb = tid & 3;

    if (tid < 128) {
        // ================= G0: layer-0 producer loop =================
        float c0 = 0.0f;
        float4 p = __ldcs((const float4*)&g_pre[br][0][grow][bg0]);
        for (int s = 0; s < TT; ++s) {
            if (s > 0)
                mbar_wait_parity(mbh0 + 8u*((s - 1) & 3), (unsigned)(((s - 1) >> 2) & 1));

            unsigned long long a01 = pack2(p.x, p.y);
            unsigned long long a23 = pack2(p.z, p.w);
            const float* hsrc = h0ring + ((s + 3) & 3) * (HH * BG);  // (s-1) mod 4; s=0 -> slot3 zeros
            #pragma unroll
            for (int k = 0; k < WREG; ++k) {
                ulonglong2 v = *(const ulonglong2*)&hsrc[k * BG];
                unsigned long long wp = pack2(wreg[k], wreg[k]);
                fma2(a01, wp, v.x);
                fma2(a23, wp, v.y);
            }
            #pragma unroll 8
            for (int kk = 0; kk < WSMK; ++kk) {
                float w = wsm[kk * HH + r];
                unsigned long long wp = pack2(w, w);
                ulonglong2 v = *(const ulonglong2*)&hsrc[(WREG + kk) * BG];
                fma2(a01, wp, v.x);
                fma2(a23, wp, v.y);
            }
            ((ulonglong2*)gall)[r] = make_ulonglong2(a01, a23);
            BAR_SYNC(1, 128);

            if (tid == 0 && s > 0) {   // G0 consumed fill s-1
                #pragma unroll
                for (uint32_t rr = 0; rr < CSZ; ++rr)
                    mbar_arrive_rk(mbf0 + 8u*((s - 1) & 3), rr);
            }

            // update
            float ip = gall[(0  + su) * BG + sb];
            float fp = gall[(32 + su) * BG + sb];
            float gp = gall[(64 + su) * BG + sb];
            float op = gall[(96 + su) * BG + sb];
            c0 = sigf(fp) * c0 + sigf(ip) * tanhfast(gp);
            float h = sigf(op) * tanhfast(c0);

            if (s >= 4) {   // backpressure: slot must be freed by all cluster consumers
                mbar_wait_parity(mbf0 + 8u*(s & 3), (unsigned)(((s >> 2) - 1) & 1));
                if (tid == 0) mbar_expect_tx(mbh0 + 8u*(s & 3), 2048u);  // re-arm fill s
            }
            uint32_t la = h0base + (uint32_t)((((s & 3) * HH + cu0 + su) * BG + sb) * 4);
            #pragma unroll
            for (uint32_t rr = 0; rr < CSZ; ++rr)
                st_async_f32(la, mbh0 + 8u*(s & 3), rr, h);

            if (s + 1 < TT)
                p = __ldcs((const float4*)&g_pre[br][s + 1][grow][bg0]);
        }
    } else {
        // ================= G1: layer-1 consumer loop =================
        float c1 = 0.0f;
        const int durb = dur[bg0 + sb];
        for (int s = 0; s < TT; ++s) {
            mbar_wait_parity(mbh0 + 8u*(s & 3), (unsigned)((s >> 2) & 1));  // h0(s) buffered
            if (s > 0) {
                const uint32_t mbp = mbh2 + 8u*((s - 1) & 1);
                mbar_wait_parity(mbp, (unsigned)(((s - 1) >> 1) & 1));      // h2(s-1)
                if (tid == 128 && s + 1 < TT) mbar_expect_tx(mbp, 2048u);   // re-arm for s+1
            }

            unsigned long long a01, a23;
            const float* hsrc;
            if (jid == 1) {
                float bb = b1sm[r];
                a01 = pack2(bb, bb); a23 = a01;
                hsrc = h0ring + (s & 3) * (HH * BG);
            } else {
                a01 = 0ull; a23 = 0ull;
                hsrc = h2buf + ((s + 1) & 1) * (HH * BG);   // h2(s-1)
            }
            #pragma unroll
            for (int k = 0; k < WREG; ++k) {
                ulonglong2 v = *(const ulonglong2*)&hsrc[k * BG];
                unsigned long long wp = pack2(wreg[k], wreg[k]);
                fma2(a01, wp, v.x);
                fma2(a23, wp, v.y);
            }
            #pragma unroll 8
            for (int kk = 0; kk < WSMK; ++kk) {
                float w = wsm[kk * HH + r];
                unsigned long long wp = pack2(w, w);
                ulonglong2 v = *(const ulonglong2*)&hsrc[(WREG + kk) * BG];
                fma2(a01, wp, v.x);
                fma2(a23, wp, v.y);
            }
            ((ulonglong2*)gall)[jid * HH + r] = make_ulonglong2(a01, a23);
            BAR_SYNC(2, 256);

            if (tid == 128) {   // G1 consumed fill s
                #pragma unroll
                for (uint32_t rr = 0; rr < CSZ; ++rr)
                    mbar_arrive_rk(mbf0 + 8u*(s & 3), rr);
            }

            if (tid < 256) {
                const float* ga = gall + 1 * HH * BG;
                const float* gb = gall + 2 * HH * BG;
                float ip = ga[(0  + su) * BG + sb] + gb[(0  + su) * BG + sb];
                float fp = ga[(32 + su) * BG + sb] + gb[(32 + su) * BG + sb];
                float gp = ga[(64 + su) * BG + sb] + gb[(64 + su) * BG + sb];
                float op = ga[(96 + su) * BG + sb] + gb[(96 + su) * BG + sb];
                c1 = sigf(fp) * c1 + sigf(ip) * tanhfast(gp);
                float h = sigf(op) * tanhfast(c1);
                uint32_t la = h2base + (uint32_t)((((s & 1) * HH + cu0 + su) * BG + sb) * 4);
                #pragma unroll
                for (uint32_t rr = 0; rr < CSZ; ++rr)
                    st_async_f32(la, mbh2 + 8u*(s & 1), rr, h);
                if (s == durb - 1) g_hf[br][cu0 + su][bg0 + sb] = h;
            }
        }
    }

    // join both groups, confirm final h2 fill delivered locally, quiesce cluster
    __syncthreads();
    mbar_wait_parity(mbh2 + 8u*((TT - 1) & 1), (unsigned)(((TT - 1) >> 1) & 1));
    CLUSTER_SYNC();
}

// ==================================================================
// Kernel 3: epilogue
// ==================================================================
__global__ void __launch_bounds__(64)
epilogue_kernel(const int* __restrict__ yv,
                const float* __restrict__ wcl, const float* __restrict__ bcl,
                const float* __restrict__ wcr, const float* __restrict__ bcr,
                const float* __restrict__ Wout, const float* __restrict__ bout,
                float* __restrict__ out)
{
    __shared__ float lsum[64];
    const int b = threadIdx.x;

    float hl[HH + 2], hr[HH + 2], y3[HH];
    hl[0] = 0.0f; hl[HH + 1] = 0.0f;
    hr[0] = 0.0f; hr[HH + 1] = 0.0f;
    for (int j = 0; j < HH; ++j) {
        hl[j + 1] = g_hf[0][j][b];
        hr[j + 1] = g_hf[1][j][b];
    }
    float wl0 = wcl[0], wl1 = wcl[1], wl2 = wcl[2], bl = bcl[0];
    float wr0 = wcr[0], wr1 = wcr[1], wr2 = wcr[2], br_ = bcr[0];
    for (int j = 0; j < HH; ++j) {
        float vl = wl0 * hl[j] + wl1 * hl[j + 1] + wl2 * hl[j + 2] + bl;
        float vr = wr0 * hr[j] + wr1 * hr[j + 1] + wr2 * hr[j + 2] + br_;
        y3[j] = vl + vr;
        out[ACT_OFF + b * HH + j] = tanhf(y3[j]) * 0.1f;
    }
    float logits[LL];
    float mx = -1e30f;
    for (int l = 0; l < LL; ++l) {
        float s = bout[l];
        for (int j = 0; j < HH; ++j) s += y3[j] * Wout[l * HH + j];
        logits[l] = s;
        mx = fmaxf(mx, s);
    }
    float den = 0.0f;
    for (int l = 0; l < LL; ++l) { logits[l] = expf(logits[l] - mx); den += logits[l]; }
    float inv = 1.0f / den;
    int yb = yv[b];
    float py = 0.0f, myloss = 0.0f;
    for (int l = 0; l < LL; ++l) {
        float pql = logits[l] * inv;
        logits[l] = pql;
        out[PRED_OFF + b * LL + l] = pql;
        if (l == yb) py = pql;
    }
    for (int l = 0; l < LL; ++l) {
        float pql = logits[l];
        float lp = fmaxf(logf(pql), -100.0f);
        float lq = fmaxf(logf(1.0f - pql), -100.0f);
        myloss += (l == yb) ? lp : lq;
    }
    int rank = 0;
    for (int l = 0; l < LL; ++l) {
        if (logits[l] > py) rank++;
        else if (logits[l] == py && l < yb) rank++;
    }
    out[ACC1_OFF + b] = (rank == 0) ? 1.0f : 0.0f;
    out[ACC3_OFF + b] = (rank < 3) ? 1.0f : 0.0f;

    lsum[b] = myloss;
    __syncthreads();
    if (b == 0) {
        float s = 0.0f;
        for (int i = 0; i < BATCH; ++i) s += lsum[i];
        out[0] = -s / (float)(BATCH * LL);
    }
}

// ==================================================================
extern "C" void kernel_launch(void* const* d_in, const int* in_sizes, int n_in,
                              void* d_out, int out_size) {
    (void)in_sizes; (void)n_in; (void)out_size;
    cudaFuncSetAttribute(pre_gemm_kernel, cudaFuncAttributeMaxDynamicSharedMemorySize,
                         GEMM_SMEM_FLOATS * (int)sizeof(float));
    cudaFuncSetAttribute(lstm_recurrent_kernel, cudaFuncAttributeMaxDynamicSharedMemorySize,
                         REC_SMEM_FLOATS * (int)sizeof(float));

    const float* xl  = (const float*)d_in[0];
    const float* xr  = (const float*)d_in[1];
    const float* xo  = (const float*)d_in[2];
    const int*   yv  = (const int*)d_in[3];
    const int*   isl = (const int*)d_in[4];
    const int*   isr = (const int*)d_in[5];
    const int*   dur = (const int*)d_in[6];

    pre_gemm_kernel<<<dim3(8, TT, 2), 128, GEMM_SMEM_FLOATS * sizeof(float)>>>(
        xl, xr, xo, isl, isr,
        (const float*)d_in[7],  (const float*)d_in[9],  (const float*)d_in[10],
        (const float*)d_in[15], (const float*)d_in[17], (const float*)d_in[18]);

    lstm_recurrent_kernel<<<128, 384, REC_SMEM_FLOATS * sizeof(float)>>>(
        (const float*)d_in[8],  (const float*)d_in[16],
        (const float*)d_in[11], (const float*)d_in[12],
        (const float*)d_in[13], (const float*)d_in[14],
        (const float*)d_in[19], (const float*)d_in[20],
        (const float*)d_in[21], (const float*)d_in[22],
        dur);

    epilogue_kernel<<<1, 64>>>(
        yv,
        (const float*)d_in[23], (const float*)d_in[24],
        (const float*)d_in[25], (const float*)d_in[26],
        (const float*)d_in[27], (const float*)d_in[28],
        (float*)d_out);
}

// round 15
// speedup vs baseline: 1.2454x; 1.2454x over previous
#include <cuda_runtime.h>
#include <math.h>
#include <stdint.h>

#define BATCH 64
#define TT    2048
#define HH    128
#define DIN   108
#define LL    37

#define BG    4      // batches per cluster
#define CSZ   4      // CTAs per cluster
#define UPC   32     // hidden units per CTA

#define WREG  120    // k-range held in registers
#define WSMK  8      // k-range held in smem

#define ACC1_OFF 1
#define ACC3_OFF 65
#define ACT_OFF  129
#define PRED_OFF (129 + BATCH*HH)

// ---------------- device scratch (static; no runtime allocation) ----------------
__device__ __align__(16) float g_pre[2][TT][512][BATCH];   // x@Wih0^T + (bih0+bhh0)
__device__ __align__(16) float g_hf[2][HH][BATCH];

__device__ __forceinline__ float sigf(float x)    { return 1.0f / (1.0f + __expf(-x)); }
__device__ __forceinline__ float tanhfast(float x){ return 2.0f / (1.0f + __expf(-2.0f * x)) - 1.0f; }

__device__ __forceinline__ unsigned long long pack2(float x, float y) {
    unsigned long long r;
    asm("mov.b64 %0, {%1, %2};" : "=l"(r) : "f"(x), "f"(y));
    return r;
}
__device__ __forceinline__ void fma2(unsigned long long& acc, unsigned long long w2,
                                     unsigned long long v2) {
    asm("fma.rn.f32x2 %0, %1, %2, %0;" : "+l"(acc) : "l"(w2), "l"(v2));
}
// async remote store, tx-tracked on the destination CTA's (phase-selected) mbarrier
__device__ __forceinline__ void st_async_f32(uint32_t saddr, uint32_t mbaddr,
                                             uint32_t rk, float v) {
    uint32_t ra, rb;
    asm volatile("mapa.shared::cluster.u32 %0, %1, %2;" : "=r"(ra) : "r"(saddr), "r"(rk));
    asm volatile("mapa.shared::cluster.u32 %0, %1, %2;" : "=r"(rb) : "r"(mbaddr), "r"(rk));
    asm volatile("st.async.shared::cluster.mbarrier::complete_tx::bytes.b32 [%0], %1, [%2];"
                 :: "r"(ra), "r"(__float_as_uint(v)), "r"(rb) : "memory");
}
__device__ __forceinline__ void mbar_expect_tx(uint32_t mbaddr, uint32_t tx) {
    asm volatile("mbarrier.arrive.expect_tx.shared.b64 _, [%0], %1;"
                 :: "r"(mbaddr), "r"(tx) : "memory");
}
__device__ __forceinline__ void mbar_wait_parity(uint32_t mbaddr, uint32_t parity) {
    uint32_t done;
    asm volatile(
        "{\n\t.reg .pred p;\n\t"
        "mbarrier.try_wait.parity.acquire.cluster.shared::cta.b64 p, [%1], %2;\n\t"
        "selp.b32 %0, 1, 0, p;\n\t}"
        : "=r"(done) : "r"(mbaddr), "r"(parity) : "memory");
    if (!done) {
        asm volatile(
            "{\n\t.reg .pred p;\n\t"
            "WL_%=:\n\t"
            "mbarrier.try_wait.parity.acquire.cluster.shared::cta.b64 p, [%0], %1, 0x989680;\n\t"
            "@p bra.uni WD_%=;\n\t"
            "bra.uni WL_%=;\n\t"
            "WD_%=:\n\t}"
            :: "r"(mbaddr), "r"(parity) : "memory");
    }
}
#define CLUSTER_SYNC() do { \
    asm volatile("barrier.cluster.arrive.aligned;" ::: "memory"); \
    asm volatile("barrier.cluster.wait.aligned;"   ::: "memory"); \
} while (0)
#define BAR_SYNC(id, cnt) asm volatile("bar.sync %0, %1;" :: "r"(id), "r"(cnt) : "memory")

// ==================================================================
// Kernel 1: precompute gate inputs  pre[br][t][row][b]
// (staging loops use direct indexing — no integer div/mod)
// ==================================================================
#define GX_XS 0
#define GX_WS (DIN*68)
#define GX_BS (GX_WS + 64*113)
#define GEMM_SMEM_FLOATS (GX_BS + 64)

__global__ void __launch_bounds__(128)
pre_gemm_kernel(const float* __restrict__ xl, const float* __restrict__ xr,
                const float* __restrict__ xo,
                const int* __restrict__ isl, const int* __restrict__ isr,
                const float* __restrict__ Wl, const float* __restrict__ bil, const float* __restrict__ bhl,
                const float* __restrict__ Wr, const float* __restrict__ bir, const float* __restrict__ bhr)
{
    extern __shared__ float sg[];
    float* xs  = sg + GX_XS;
    float* Wsm = sg + GX_WS;
    float* bsm = sg + GX_BS;

    const int rb  = blockIdx.x;
    const int t   = blockIdx.y;
    const int br  = blockIdx.z;
    const int tid = threadIdx.x;

    const float* xh  = br ? xr  : xl;
    const int*   ish = br ? isr : isl;
    const float* W   = br ? Wr  : Wl;
    const float* bi  = br ? bir : bil;
    const float* bh  = br ? bhr : bhl;

    // x staging: thread = (batch b, half) ; 54 k each, no div/mod
    {
        const int b = tid >> 1, half = tid & 1;
        const int k0 = half * 54;
        const float* xrow = xh + (size_t)(b * TT + t) * 99;
        const float* orow = xo + (size_t)(b * TT + t) * 9;
        const float msk = (ish[b] != 0) ? 1.0f : 0.0f;
        #pragma unroll 6
        for (int k = k0; k < k0 + 54; ++k) {
            float v = (k < 99) ? xrow[k] * msk : orow[k - 99];
            xs[k * 68 + b] = v;
        }
    }
    // W staging: thread = (row lr, half) ; 54 k each
    {
        const int lr = tid >> 1, half = tid & 1;
        const float* wrow = W + (size_t)(rb * 64 + lr) * DIN;
        const int k0 = half * 54;
        #pragma unroll 6
        for (int k = k0; k < k0 + 54; ++k)
            Wsm[lr * 113 + k] = wrow[k];
    }
    if (tid < 64) bsm[tid] = bi[rb * 64 + tid] + bh[rb * 64 + tid];
    __syncthreads();

    const int rg = tid >> 4;
    const int b4 = (tid & 15) * 4;

    float4 acc[8];
    #pragma unroll
    for (int j = 0; j < 8; ++j) {
        float bb = bsm[rg * 8 + j];
        acc[j] = make_float4(bb, bb, bb, bb);
    }
    #pragma unroll 4
    for (int k = 0; k < DIN; ++k) {
        float4 xv = *(const float4*)&xs[k * 68 + b4];
        #pragma unroll
        for (int j = 0; j < 8; ++j) {
            float w = Wsm[(rg * 8 + j) * 113 + k];
            acc[j].x += w * xv.x; acc[j].y += w * xv.y;
            acc[j].z += w * xv.z; acc[j].w += w * xv.w;
        }
    }
    #pragma unroll
    for (int j = 0; j < 8; ++j) {
        int row = rb * 64 + rg * 8 + j;
        *(float4*)&g_pre[br][t][row][b4] = acc[j];
    }
}

// ==================================================================
// Kernel 2: cluster-parallel wavefront recurrence (R12 protocol verbatim).
// Double-buffered st.async tx-tracked mbarriers; balanced 3-job split.
// Deltas vs R12: WREG 120 / WSMK 8; prefetch issued before the fma chain.
// ==================================================================
#define WS_OFF  0                        // ws[3][WSMK][128]
#define B1_OFF  (WS_OFF + 3*WSMK*HH)     // 128
#define H0_OFF  (B1_OFF + HH)            // 2 slots x 128 units x 4
#define H2_OFF  (H0_OFF + 2*HH*BG)
#define G_OFF   (H2_OFF + 2*HH*BG)       // g[3][128][4]
#define MB_OFF  (G_OFF + 3*HH*BG)        // 2 x u64 mbarrier (4 floats)
#define REC_SMEM_FLOATS (MB_OFF + 4)

__global__ void __launch_bounds__(384, 1) __cluster_dims__(CSZ, 1, 1)
lstm_recurrent_kernel(const float* __restrict__ Whh0_l, const float* __restrict__ Whh0_r,
                      const float* __restrict__ Wih1_l, const float* __restrict__ Whh1_l,
                      const float* __restrict__ bih1_l, const float* __restrict__ bhh1_l,
                      const float* __restrict__ Wih1_r, const float* __restrict__ Whh1_r,
                      const float* __restrict__ bih1_r, const float* __restrict__ bhh1_r,
                      const int* __restrict__ dur)
{
    extern __shared__ float sm[];
    float* wsAll = sm + WS_OFF;
    float* b1sm  = sm + B1_OFF;
    float* h0buf = sm + H0_OFF;    // [slot][unit(128)][b(4)]
    float* h2buf = sm + H2_OFF;
    float* gall  = sm + G_OFF;     // [jid][row(128)][b(4)]

    const int tid = threadIdx.x;
    const int blk = blockIdx.x;
    const int cid = blk >> 2;            // cluster id 0..31
    const int br  = cid >> 4;            // branch
    const int bg0 = (cid & 15) * BG;     // first batch of group

    uint32_t rank;
    asm("mov.u32 %0, %%cluster_ctarank;" : "=r"(rank));
    const int cu0 = (int)rank * UPC;

    const float* Whh0 = br ? Whh0_r : Whh0_l;
    const float* Wih1 = br ? Wih1_r : Wih1_l;
    const float* Whh1 = br ? Whh1_r : Whh1_l;
    const float* bi1  = br ? bih1_r : bih1_l;
    const float* bh1  = br ? bhh1_r : bhh1_l;

    const int jid = tid >> 7;            // 0=L0, 1=L1a(Wih1), 2=L1b(Whh1)
    const int r   = tid & 127;           // gate-row
    const int grow = (r >> 5) * HH + cu0 + (r & 31);

    const float* mat = (jid == 0) ? Whh0 : ((jid == 1) ? Wih1 : Whh1);

    // ---- weights: k [0,WREG) -> registers; k [WREG,128) -> smem [kk][r] ----
    float wreg[WREG];
    #pragma unroll
    for (int k = 0; k < WREG; ++k) wreg[k] = mat[grow * HH + k];
    float* wsm = wsAll + jid * WSMK * HH;
    #pragma unroll
    for (int kk = 0; kk < WSMK; ++kk) wsm[kk * HH + r] = mat[grow * HH + WREG + kk];

    if (tid < HH) {
        int gr = (tid >> 5) * HH + cu0 + (tid & 31);
        b1sm[tid] = bi1[gr] + bh1[gr];
    }
    for (int i = tid; i < 2 * HH * BG; i += 384) { h0buf[i] = 0.0f; h2buf[i] = 0.0f; }

    const uint32_t mbar0 = (uint32_t)__cvta_generic_to_shared(sm + MB_OFF);
    const uint32_t mbar1 = mbar0 + 8u;
    if (tid == 0) {
        asm volatile("mbarrier.init.shared.b64 [%0], %1;" :: "r"(mbar0), "r"(1) : "memory");
        asm volatile("mbarrier.init.shared.b64 [%0], %1;" :: "r"(mbar1), "r"(1) : "memory");
        mbar_expect_tx(mbar0, 2048u);   // phase 0: h0 only
        mbar_expect_tx(mbar1, 4096u);   // phase 1: h0 + h2
    }
    __syncthreads();
    CLUSTER_SYNC();   // barriers armed + zeros + smem weights visible before step 0

    const uint32_t h0base = (uint32_t)__cvta_generic_to_shared(h0buf);
    const uint32_t h2base = (uint32_t)__cvta_generic_to_shared(h2buf);

    const int su = (tid & 127) >> 2;     // unit
    const int sb = tid & 3;              // batch
    float c0 = 0.0f, c1 = 0.0f;
    const int durb = dur[bg0 + sb];

    float4 p = make_float4(0.f, 0.f, 0.f, 0.f);
    if (jid == 0) p = __ldcs((const float4*)&g_pre[br][0][grow][bg0]);

    for (int s = 0; s <= TT; ++s) {
        if (s > 0) {
            const uint32_t mbprev = ((s - 1) & 1) ? mbar1 : mbar0;
            mbar_wait_parity(mbprev, (unsigned)(((s - 1) >> 1) & 1));   // phase s-1 delivered
            if (tid == 0 && s + 1 <= TT) {  // re-arm this barrier for phase s+1
                uint32_t tx = ((s + 1 < TT) ? 2048u : 0u) + 2048u;      // s+1 >= 1 always
                mbar_expect_tx(mbprev, tx);
            }
        }
        const uint32_t mbcur = (s & 1) ? mbar1 : mbar0;

        const float* h0prev = h0buf + ((s + 1) & 1) * (HH * BG);
        const float* h2prev = h2buf + ((s + 1) & 1) * (HH * BG);

        // ---- gate partial loops ----
        const bool active = (jid == 0) ? (s < TT) : (s >= 1);
        if (active) {
            unsigned long long a01, a23;
            float4 pnext = p;
            if (jid == 0) {
                a01 = pack2(p.x, p.y); a23 = pack2(p.z, p.w);
                // prefetch NOW — the 128-iter fma chain below hides the DRAM latency
                if (s + 1 < TT)
                    pnext = __ldcs((const float4*)&g_pre[br][s + 1][grow][bg0]);
            } else if (jid == 1) {
                float bb = b1sm[r];
                a01 = pack2(bb, bb); a23 = a01;
            } else {
                a01 = 0ull; a23 = 0ull;
            }
            const float* hsrc = (jid == 2) ? h2prev : h0prev;
            #pragma unroll
            for (int k = 0; k < WREG; ++k) {
                ulonglong2 v = *(const ulonglong2*)&hsrc[k * BG];
                unsigned long long wp = pack2(wreg[k], wreg[k]);
                fma2(a01, wp, v.x);
                fma2(a23, wp, v.y);
            }
            #pragma unroll
            for (int kk = 0; kk < WSMK; ++kk) {
                float w = wsm[kk * HH + r];
                unsigned long long wp = pack2(w, w);
                ulonglong2 v = *(const ulonglong2*)&hsrc[(WREG + kk) * BG];
                fma2(a01, wp, v.x);
                fma2(a23, wp, v.y);
            }
            ((ulonglong2*)gall)[jid * HH + r] = make_ulonglong2(a01, a23);
            if (jid == 0) p = pnext;
        }

        // ---- per-job-group sync (decouple L0 from L1 tail) ----
        if (jid == 0) BAR_SYNC(1, 128);
        else          BAR_SYNC(2, 256);

        // ---- state updates + tx-tracked DSMEM broadcast (phase s -> mbar[s&1]) ----
        if (tid < 128) {
            if (s < TT) {
                const float* g0 = gall;
                float ip = g0[(0  + su) * BG + sb];
                float fp = g0[(32 + su) * BG + sb];
                float gp = g0[(64 + su) * BG + sb];
                float op = g0[(96 + su) * BG + sb];
                c0 = sigf(fp) * c0 + sigf(ip) * tanhfast(gp);
                float h = sigf(op) * tanhfast(c0);
                uint32_t la = h0base + (uint32_t)((((s & 1) * HH + cu0 + su) * BG + sb) * 4);
                #pragma unroll
                for (uint32_t rr = 0; rr < CSZ; ++rr) st_async_f32(la, mbcur, rr, h);
            }
        } else if (tid < 256) {
            if (s >= 1) {
                const float* ga = gall + 1 * HH * BG;
                const float* gb = gall + 2 * HH * BG;
                float ip = ga[(0  + su) * BG + sb] + gb[(0  + su) * BG + sb];
                float fp = ga[(32 + su) * BG + sb] + gb[(32 + su) * BG + sb];
                float gp = ga[(64 + su) * BG + sb] + gb[(64 + su) * BG + sb];
                float op = ga[(96 + su) * BG + sb] + gb[(96 + su) * BG + sb];
                c1 = sigf(fp) * c1 + sigf(ip) * tanhfast(gp);
                float h = sigf(op) * tanhfast(c1);
                uint32_t la = h2base + (uint32_t)((((s & 1) * HH + cu0 + su) * BG + sb) * 4);
                #pragma unroll
                for (uint32_t rr = 0; rr < CSZ; ++rr) st_async_f32(la, mbcur, rr, h);
                if (s == durb) g_hf[br][cu0 + su][bg0 + sb] = h;
            }
        }
    }

    // drain final phase, invalidate barriers, full cluster quiesce before exit
    mbar_wait_parity((TT & 1) ? mbar1 : mbar0, (unsigned)((TT >> 1) & 1));
    __syncthreads();
    if (tid == 0) {
        asm volatile("mbarrier.inval.shared.b64 [%0];" :: "r"(mbar0) : "memory");
        asm volatile("mbarrier.inval.shared.b64 [%0];" :: "r"(mbar1) : "memory");
    }
    CLUSTER_SYNC();
}

// ==================================================================
// Kernel 3: epilogue
// ==================================================================
__global__ void __launch_bounds__(64)
epilogue_kernel(const int* __restrict__ yv,
                const float* __restrict__ wcl, const float* __restrict__ bcl,
                const float* __restrict__ wcr, const float* __restrict__ bcr,
                const float* __restrict__ Wout, const float* __restrict__ bout,
                float* __restrict__ out)
{
    __shared__ float lsum[64];
    const int b = threadIdx.x;

    float hl[HH + 2], hr[HH + 2], y3[HH];
    hl[0] = 0.0f; hl[HH + 1] = 0.0f;
    hr[0] = 0.0f; hr[HH + 1] = 0.0f;
    for (int j = 0; j < HH; ++j) {
        hl[j + 1] = g_hf[0][j][b];
        hr[j + 1] = g_hf[1][j][b];
    }
    float wl0 = wcl[0], wl1 = wcl[1], wl2 = wcl[2], bl = bcl[0];
    float wr0 = wcr[0], wr1 = wcr[1], wr2 = wcr[2], br_ = bcr[0];
    for (int j = 0; j < HH; ++j) {
        float vl = wl0 * hl[j] + wl1 * hl[j + 1] + wl2 * hl[j + 2] + bl;
        float vr = wr0 * hr[j] + wr1 * hr[j + 1] + wr2 * hr[j + 2] + br_;
        y3[j] = vl + vr;
        out[ACT_OFF + b * HH + j] = tanhf(y3[j]) * 0.1f;
    }
    float logits[LL];
    float mx = -1e30f;
    for (int l = 0; l < LL; ++l) {
        float s = bout[l];
        for (int j = 0; j < HH; ++j) s += y3[j] * Wout[l * HH + j];
        logits[l] = s;
        mx = fmaxf(mx, s);
    }
    float den = 0.0f;
    for (int l = 0; l < LL; ++l) { logits[l] = expf(logits[l] - mx); den += logits[l]; }
    float inv = 1.0f / den;
    int yb = yv[b];
    float py = 0.0f, myloss = 0.0f;
    for (int l = 0; l < LL; ++l) {
        float pql = logits[l] * inv;
        logits[l] = pql;
        out[PRED_OFF + b * LL + l] = pql;
        if (l == yb) py = pql;
    }
    for (int l = 0; l < LL; ++l) {
        float pql = logits[l];
        float lp = fmaxf(logf(pql), -100.0f);
        float lq = fmaxf(logf(1.0f - pql), -100.0f);
        myloss += (l == yb) ? lp : lq;
    }
    int rank = 0;
    for (int l = 0; l < LL; ++l) {
        if (logits[l] > py) rank++;
        else if (logits[l] == py && l < yb) rank++;
    }
    out[ACC1_OFF + b] = (rank == 0) ? 1.0f : 0.0f;
    out[ACC3_OFF + b] = (rank < 3) ? 1.0f : 0.0f;

    lsum[b] = myloss;
    __syncthreads();
    if (b == 0) {
        float s = 0.0f;
        for (int i = 0; i < BATCH; ++i) s += lsum[i];
        out[0] = -s / (float)(BATCH * LL);
    }
}

// ==================================================================
extern "C" void kernel_launch(void* const* d_in, const int* in_sizes, int n_in,
                              void* d_out, int out_size) {
    (void)in_sizes; (void)n_in; (void)out_size;
    cudaFuncSetAttribute(pre_gemm_kernel, cudaFuncAttributeMaxDynamicSharedMemorySize,
                         GEMM_SMEM_FLOATS * (int)sizeof(float));
    cudaFuncSetAttribute(lstm_recurrent_kernel, cudaFuncAttributeMaxDynamicSharedMemorySize,
                         REC_SMEM_FLOATS * (int)sizeof(float));

    const float* xl  = (const float*)d_in[0];
    const float* xr  = (const float*)d_in[1];
    const float* xo  = (const float*)d_in[2];
    const int*   yv  = (const int*)d_in[3];
    const int*   isl = (const int*)d_in[4];
    const int*   isr = (const int*)d_in[5];
    const int*   dur = (const int*)d_in[6];

    pre_gemm_kernel<<<dim3(8, TT, 2), 128, GEMM_SMEM_FLOATS * sizeof(float)>>>(
        xl, xr, xo, isl, isr,
        (const float*)d_in[7],  (const float*)d_in[9],  (const float*)d_in[10],
        (const float*)d_in[15], (const float*)d_in[17], (const float*)d_in[18]);

    lstm_recurrent_kernel<<<128, 384, REC_SMEM_FLOATS * sizeof(float)>>>(
        (const float*)d_in[8],  (const float*)d_in[16],
        (const float*)d_in[11], (const float*)d_in[12],
        (const float*)d_in[13], (const float*)d_in[14],
        (const float*)d_in[19], (const float*)d_in[20],
        (const float*)d_in[21], (const float*)d_in[22],
        dur);

    epilogue_kernel<<<1, 64>>>(
        yv,
        (const float*)d_in[23], (const float*)d_in[24],
        (const float*)d_in[25], (const float*)d_in[26],
        (const float*)d_in[27], (const float*)d_in[28],
        (float*)d_out);
}

// round 16
// speedup vs baseline: 1.4498x; 1.1642x over previous
#include <cuda_runtime.h>
#include <math.h>
#include <stdint.h>

#define BATCH 64
#define TT    2048
#define HH    128
#define DIN   108
#define LL    37

#define BG    4      // batches per cluster
#define CSZ   4      // CTAs per cluster
#define UPC   32     // hidden units per CTA

#define WREG  112    // k-range held in registers
#define WSMK  16     // k-range held in smem

#define ACC1_OFF 1
#define ACC3_OFF 65
#define ACT_OFF  129
#define PRED_OFF (129 + BATCH*HH)

// ---------------- device scratch (static; no runtime allocation) ----------------
__device__ __align__(16) float g_pre[2][TT][512][BATCH];   // x@Wih0^T + (bih0+bhh0)
__device__ __align__(16) float g_hf[2][HH][BATCH];

__device__ __forceinline__ float sigf(float x)    { return 1.0f / (1.0f + __expf(-x)); }
__device__ __forceinline__ float tanhfast(float x){ return 2.0f / (1.0f + __expf(-2.0f * x)) - 1.0f; }

__device__ __forceinline__ unsigned long long pack2(float x, float y) {
    unsigned long long r;
    asm("mov.b64 %0, {%1, %2};" : "=l"(r) : "f"(x), "f"(y));
    return r;
}
__device__ __forceinline__ void fma2(unsigned long long& acc, unsigned long long w2,
                                     unsigned long long v2) {
    asm("fma.rn.f32x2 %0, %1, %2, %0;" : "+l"(acc) : "l"(w2), "l"(v2));
}
// mapa: translate local SMEM address to rank rk's window (loop-invariant, hoisted)
__device__ __forceinline__ uint32_t mapa_rk(uint32_t saddr, uint32_t rk) {
    uint32_t ra;
    asm volatile("mapa.shared::cluster.u32 %0, %1, %2;" : "=r"(ra) : "r"(saddr), "r"(rk));
    return ra;
}
// async remote store with PRE-TRANSLATED addresses
__device__ __forceinline__ void st_async_pre(uint32_t ra, uint32_t rb, float v) {
    asm volatile("st.async.shared::cluster.mbarrier::complete_tx::bytes.b32 [%0], %1, [%2];"
                 :: "r"(ra), "r"(__float_as_uint(v)), "r"(rb) : "memory");
}
__device__ __forceinline__ void mbar_expect_tx(uint32_t mbaddr, uint32_t tx) {
    asm volatile("mbarrier.arrive.expect_tx.shared.b64 _, [%0], %1;"
                 :: "r"(mbaddr), "r"(tx) : "memory");
}
__device__ __forceinline__ void mbar_wait_parity(uint32_t mbaddr, uint32_t parity) {
    uint32_t done;
    asm volatile(
        "{\n\t.reg .pred p;\n\t"
        "mbarrier.try_wait.parity.acquire.cluster.shared::cta.b64 p, [%1], %2;\n\t"
        "selp.b32 %0, 1, 0, p;\n\t}"
        : "=r"(done) : "r"(mbaddr), "r"(parity) : "memory");
    if (!done) {
        asm volatile(
            "{\n\t.reg .pred p;\n\t"
            "WL_%=:\n\t"
            "mbarrier.try_wait.parity.acquire.cluster.shared::cta.b64 p, [%0], %1, 0x989680;\n\t"
            "@p bra.uni WD_%=;\n\t"
            "bra.uni WL_%=;\n\t"
            "WD_%=:\n\t}"
            :: "r"(mbaddr), "r"(parity) : "memory");
    }
}
#define CLUSTER_SYNC() do { \
    asm volatile("barrier.cluster.arrive.aligned;" ::: "memory"); \
    asm volatile("barrier.cluster.wait.aligned;"   ::: "memory"); \
} while (0)
#define BAR_SYNC(id, cnt) asm volatile("bar.sync %0, %1;" :: "r"(id), "r"(cnt) : "memory")

// ==================================================================
// Kernel 1: precompute gate inputs  pre[br][t][row][b]  (R12 original)
// ==================================================================
#define GX_XS 0
#define GX_WS (DIN*68)
#define GX_BS (GX_WS + 64*113)
#define GEMM_SMEM_FLOATS (GX_BS + 64)

__global__ void __launch_bounds__(128)
pre_gemm_kernel(const float* __restrict__ xl, const float* __restrict__ xr,
                const float* __restrict__ xo,
                const int* __restrict__ isl, const int* __restrict__ isr,
                const float* __restrict__ Wl, const float* __restrict__ bil, const float* __restrict__ bhl,
                const float* __restrict__ Wr, const float* __restrict__ bir, const float* __restrict__ bhr)
{
    extern __shared__ float sg[];
    float* xs  = sg + GX_XS;
    float* Wsm = sg + GX_WS;
    float* bsm = sg + GX_BS;

    const int rb  = blockIdx.x;
    const int t   = blockIdx.y;
    const int br  = blockIdx.z;
    const int tid = threadIdx.x;

    const float* xh  = br ? xr  : xl;
    const int*   ish = br ? isr : isl;
    const float* W   = br ? Wr  : Wl;
    const float* bi  = br ? bir : bil;
    const float* bh  = br ? bhr : bhl;

    for (int i = tid; i < BATCH * DIN; i += 128) {
        int b = i / DIN, k = i - b * DIN;
        float v;
        if (k < 99) v = xh[(b * TT + t) * 99 + k] * ((ish[b] != 0) ? 1.0f : 0.0f);
        else        v = xo[(b * TT + t) * 9 + (k - 99)];
        xs[k * 68 + b] = v;
    }
    for (int i = tid; i < 64 * DIN; i += 128) {
        int lr = i / DIN, k = i - lr * DIN;
        Wsm[lr * 113 + k] = W[(rb * 64 + lr) * DIN + k];
    }
    if (tid < 64) bsm[tid] = bi[rb * 64 + tid] + bh[rb * 64 + tid];
    __syncthreads();

    const int rg = tid >> 4;
    const int b4 = (tid & 15) * 4;

    float4 acc[8];
    #pragma unroll
    for (int j = 0; j < 8; ++j) {
        float bb = bsm[rg * 8 + j];
        acc[j] = make_float4(bb, bb, bb, bb);
    }
    #pragma unroll 4
    for (int k = 0; k < DIN; ++k) {
        float4 xv = *(const float4*)&xs[k * 68 + b4];
        #pragma unroll
        for (int j = 0; j < 8; ++j) {
            float w = Wsm[(rg * 8 + j) * 113 + k];
            acc[j].x += w * xv.x; acc[j].y += w * xv.y;
            acc[j].z += w * xv.z; acc[j].w += w * xv.w;
        }
    }
    #pragma unroll
    for (int j = 0; j < 8; ++j) {
        int row = rb * 64 + rg * 8 + j;
        *(float4*)&g_pre[br][t][row][b4] = acc[j];
    }
}

// ==================================================================
// Kernel 2: cluster-parallel wavefront recurrence (R12 protocol).
// ONLY delta vs R12: mapa address translations hoisted out of the loop.
// ==================================================================
#define WS_OFF  0                        // ws[3][WSMK][128]
#define B1_OFF  (WS_OFF + 3*WSMK*HH)     // 128
#define H0_OFF  (B1_OFF + HH)            // 2 slots x 128 units x 4
#define H2_OFF  (H0_OFF + 2*HH*BG)
#define G_OFF   (H2_OFF + 2*HH*BG)       // g[3][128][4]
#define MB_OFF  (G_OFF + 3*HH*BG)        // 2 x u64 mbarrier (4 floats)
#define REC_SMEM_FLOATS (MB_OFF + 4)

__global__ void __launch_bounds__(384, 1) __cluster_dims__(CSZ, 1, 1)
lstm_recurrent_kernel(const float* __restrict__ Whh0_l, const float* __restrict__ Whh0_r,
                      const float* __restrict__ Wih1_l, const float* __restrict__ Whh1_l,
                      const float* __restrict__ bih1_l, const float* __restrict__ bhh1_l,
                      const float* __restrict__ Wih1_r, const float* __restrict__ Whh1_r,
                      const float* __restrict__ bih1_r, const float* __restrict__ bhh1_r,
                      const int* __restrict__ dur)
{
    extern __shared__ float sm[];
    float* wsAll = sm + WS_OFF;
    float* b1sm  = sm + B1_OFF;
    float* h0buf = sm + H0_OFF;    // [slot][unit(128)][b(4)]
    float* h2buf = sm + H2_OFF;
    float* gall  = sm + G_OFF;     // [jid][row(128)][b(4)]

    const int tid = threadIdx.x;
    const int blk = blockIdx.x;
    const int cid = blk >> 2;            // cluster id 0..31
    const int br  = cid >> 4;            // branch
    const int bg0 = (cid & 15) * BG;     // first batch of group

    uint32_t rank;
    asm("mov.u32 %0, %%cluster_ctarank;" : "=r"(rank));
    const int cu0 = (int)rank * UPC;

    const float* Whh0 = br ? Whh0_r : Whh0_l;
    const float* Wih1 = br ? Wih1_r : Wih1_l;
    const float* Whh1 = br ? Whh1_r : Whh1_l;
    const float* bi1  = br ? bih1_r : bih1_l;
    const float* bh1  = br ? bhh1_r : bhh1_l;

    const int jid = tid >> 7;            // 0=L0, 1=L1a(Wih1), 2=L1b(Whh1)
    const int r   = tid & 127;           // gate-row
    const int grow = (r >> 5) * HH + cu0 + (r & 31);

    const float* mat = (jid == 0) ? Whh0 : ((jid == 1) ? Wih1 : Whh1);

    // ---- weights: k [0,WREG) -> registers; k [WREG,128) -> smem [kk][r] ----
    float wreg[WREG];
    #pragma unroll
    for (int k = 0; k < WREG; ++k) wreg[k] = mat[grow * HH + k];
    float* wsm = wsAll + jid * WSMK * HH;
    for (int kk = 0; kk < WSMK; ++kk) wsm[kk * HH + r] = mat[grow * HH + WREG + kk];

    if (tid < HH) {
        int gr = (tid >> 5) * HH + cu0 + (tid & 31);
        b1sm[tid] = bi1[gr] + bh1[gr];
    }
    for (int i = tid; i < 2 * HH * BG; i += 384) { h0buf[i] = 0.0f; h2buf[i] = 0.0f; }

    const uint32_t mbar0 = (uint32_t)__cvta_generic_to_shared(sm + MB_OFF);
    const uint32_t mbar1 = mbar0 + 8u;
    if (tid == 0) {
        asm volatile("mbarrier.init.shared.b64 [%0], %1;" :: "r"(mbar0), "r"(1) : "memory");
        asm volatile("mbarrier.init.shared.b64 [%0], %1;" :: "r"(mbar1), "r"(1) : "memory");
        mbar_expect_tx(mbar0, 2048u);   // phase 0: h0 only
        mbar_expect_tx(mbar1, 4096u);   // phase 1: h0 + h2
    }
    __syncthreads();
    CLUSTER_SYNC();   // barriers armed + zeros + smem weights visible before step 0

    const int su = (tid & 127) >> 2;     // unit
    const int sb = tid & 3;              // batch
    float c0 = 0.0f, c1 = 0.0f;
    const int durb = dur[bg0 + sb];

    // ---- HOISTED remote-address translation (loop-invariant per thread) ----
    // hrem[rr]: this thread's destination slot-0 address in rank rr's window;
    // +HH*BG*4 bytes selects slot 1. mbrem0/1: the two barriers in rank rr.
    uint32_t hrem[CSZ], mbrem0[CSZ], mbrem1[CSZ];
    {
        const uint32_t hbase = (tid < 128)
            ? (uint32_t)__cvta_generic_to_shared(h0buf)
            : (uint32_t)__cvta_generic_to_shared(h2buf);
        const uint32_t myoff = (uint32_t)(((cu0 + su) * BG + sb) * 4);
        #pragma unroll
        for (uint32_t rr = 0; rr < CSZ; ++rr) {
            hrem[rr]   = mapa_rk(hbase, rr) + myoff;
            mbrem0[rr] = mapa_rk(mbar0, rr);
            mbrem1[rr] = mapa_rk(mbar1, rr);
        }
    }

    float4 p = make_float4(0.f, 0.f, 0.f, 0.f);
    if (jid == 0) p = __ldcs((const float4*)&g_pre[br][0][grow][bg0]);

    for (int s = 0; s <= TT; ++s) {
        if (s > 0) {
            const uint32_t mbprev = ((s - 1) & 1) ? mbar1 : mbar0;
            mbar_wait_parity(mbprev, (unsigned)(((s - 1) >> 1) & 1));   // phase s-1 delivered
            if (tid == 0 && s + 1 <= TT) {  // re-arm this barrier for phase s+1
                uint32_t tx = ((s + 1 < TT) ? 2048u : 0u) + 2048u;
                mbar_expect_tx(mbprev, tx);
            }
        }

        const float* h0prev = h0buf + ((s + 1) & 1) * (HH * BG);
        const float* h2prev = h2buf + ((s + 1) & 1) * (HH * BG);

        // ---- gate partial loops ----
        const bool active = (jid == 0) ? (s < TT) : (s >= 1);
        if (active) {
            unsigned long long a01, a23;
            if (jid == 0) {
                a01 = pack2(p.x, p.y); a23 = pack2(p.z, p.w);
            } else if (jid == 1) {
                float bb = b1sm[r];
                a01 = pack2(bb, bb); a23 = a01;
            } else {
                a01 = 0ull; a23 = 0ull;
            }
            const float* hsrc = (jid == 2) ? h2prev : h0prev;
            #pragma unroll
            for (int k = 0; k < WREG; ++k) {
                ulonglong2 v = *(const ulonglong2*)&hsrc[k * BG];
                unsigned long long wp = pack2(wreg[k], wreg[k]);
                fma2(a01, wp, v.x);
                fma2(a23, wp, v.y);
            }
            #pragma unroll 8
            for (int kk = 0; kk < WSMK; ++kk) {
                float w = wsm[kk * HH + r];
                unsigned long long wp = pack2(w, w);
                ulonglong2 v = *(const ulonglong2*)&hsrc[(WREG + kk) * BG];
                fma2(a01, wp, v.x);
                fma2(a23, wp, v.y);
            }
            ((ulonglong2*)gall)[jid * HH + r] = make_ulonglong2(a01, a23);
        }

        // ---- per-job-group sync (decouple L0 from L1 tail) ----
        if (jid == 0) BAR_SYNC(1, 128);
        else          BAR_SYNC(2, 256);

        const uint32_t slotoff = (uint32_t)((s & 1) * (HH * BG) * 4);

        // ---- state updates + tx-tracked DSMEM broadcast (pre-translated) ----
        if (tid < 128) {
            if (s < TT) {
                const float* g0 = gall;
                float ip = g0[(0  + su) * BG + sb];
                float fp = g0[(32 + su) * BG + sb];
                float gp = g0[(64 + su) * BG + sb];
                float op = g0[(96 + su) * BG + sb];
                c0 = sigf(fp) * c0 + sigf(ip) * tanhfast(gp);
                float h = sigf(op) * tanhfast(c0);
                #pragma unroll
                for (uint32_t rr = 0; rr < CSZ; ++rr)
                    st_async_pre(hrem[rr] + slotoff,
                                 (s & 1) ? mbrem1[rr] : mbrem0[rr], h);
            }
        } else if (tid < 256) {
            if (s >= 1) {
                const float* ga = gall + 1 * HH * BG;
                const float* gb = gall + 2 * HH * BG;
                float ip = ga[(0  + su) * BG + sb] + gb[(0  + su) * BG + sb];
                float fp = ga[(32 + su) * BG + sb] + gb[(32 + su) * BG + sb];
                float gp = ga[(64 + su) * BG + sb] + gb[(64 + su) * BG + sb];
                float op = ga[(96 + su) * BG + sb] + gb[(96 + su) * BG + sb];
                c1 = sigf(fp) * c1 + sigf(ip) * tanhfast(gp);
                float h = sigf(op) * tanhfast(c1);
                #pragma unroll
                for (uint32_t rr = 0; rr < CSZ; ++rr)
                    st_async_pre(hrem[rr] + slotoff,
                                 (s & 1) ? mbrem1[rr] : mbrem0[rr], h);
                if (s == durb) g_hf[br][cu0 + su][bg0 + sb] = h;
            }
        }

        // prefetch next step's pre-GEMM inputs (R12 position)
        if (jid == 0 && s + 1 < TT)
            p = __ldcs((const float4*)&g_pre[br][s + 1][grow][bg0]);
    }

    // drain final phase, invalidate barriers, full cluster quiesce before exit
    mbar_wait_parity((TT & 1) ? mbar1 : mbar0, (unsigned)((TT >> 1) & 1));
    __syncthreads();
    if (tid == 0) {
        asm volatile("mbarrier.inval.shared.b64 [%0];" :: "r"(mbar0) : "memory");
        asm volatile("mbarrier.inval.shared.b64 [%0];" :: "r"(mbar1) : "memory");
    }
    CLUSTER_SYNC();
}

// ==================================================================
// Kernel 3: epilogue
// ==================================================================
__global__ void __launch_bounds__(64)
epilogue_kernel(const int* __restrict__ yv,
                const float* __restrict__ wcl, const float* __restrict__ bcl,
                const float* __restrict__ wcr, const float* __restrict__ bcr,
                const float* __restrict__ Wout, const float* __restrict__ bout,
                float* __restrict__ out)
{
    __shared__ float lsum[64];
    const int b = threadIdx.x;

    float hl[HH + 2], hr[HH + 2], y3[HH];
    hl[0] = 0.0f; hl[HH + 1] = 0.0f;
    hr[0] = 0.0f; hr[HH + 1] = 0.0f;
    for (int j = 0; j < HH; ++j) {
        hl[j + 1] = g_hf[0][j][b];
        hr[j + 1] = g_hf[1][j][b];
    }
    float wl0 = wcl[0], wl1 = wcl[1], wl2 = wcl[2], bl = bcl[0];
    float wr0 = wcr[0], wr1 = wcr[1], wr2 = wcr[2], br_ = bcr[0];
    for (int j = 0; j < HH; ++j) {
        float vl = wl0 * hl[j] + wl1 * hl[j + 1] + wl2 * hl[j + 2] + bl;
        float vr = wr0 * hr[j] + wr1 * hr[j + 1] + wr2 * hr[j + 2] + br_;
        y3[j] = vl + vr;
        out[ACT_OFF + b * HH + j] = tanhf(y3[j]) * 0.1f;
    }
    float logits[LL];
    float mx = -1e30f;
    for (int l = 0; l < LL; ++l) {
        float s = bout[l];
        for (int j = 0; j < HH; ++j) s += y3[j] * Wout[l * HH + j];
        logits[l] = s;
        mx = fmaxf(mx, s);
    }
    float den = 0.0f;
    for (int l = 0; l < LL; ++l) { logits[l] = expf(logits[l] - mx); den += logits[l]; }
    float inv = 1.0f / den;
    int yb = yv[b];
    float py = 0.0f, myloss = 0.0f;
    for (int l = 0; l < LL; ++l) {
        float pql = logits[l] * inv;
        logits[l] = pql;
        out[PRED_OFF + b * LL + l] = pql;
        if (l == yb) py = pql;
    }
    for (int l = 0; l < LL; ++l) {
        float pql = logits[l];
        float lp = fmaxf(logf(pql), -100.0f);
        float lq = fmaxf(logf(1.0f - pql), -100.0f);
        myloss += (l == yb) ? lp : lq;
    }
    int rank = 0;
    for (int l = 0; l < LL; ++l) {
        if (logits[l] > py) rank++;
        else if (logits[l] == py && l < yb) rank++;
    }
    out[ACC1_OFF + b] = (rank == 0) ? 1.0f : 0.0f;
    out[ACC3_OFF + b] = (rank < 3) ? 1.0f : 0.0f;

    lsum[b] = myloss;
    __syncthreads();
    if (b == 0) {
        float s = 0.0f;
        for (int i = 0; i < BATCH; ++i) s += lsum[i];
        out[0] = -s / (float)(BATCH * LL);
    }
}

// ==================================================================
extern "C" void kernel_launch(void* const* d_in, const int* in_sizes, int n_in,
                              void* d_out, int out_size) {
    (void)in_sizes; (void)n_in; (void)out_size;
    cudaFuncSetAttribute(pre_gemm_kernel, cudaFuncAttributeMaxDynamicSharedMemorySize,
                         GEMM_SMEM_FLOATS * (int)sizeof(float));
    cudaFuncSetAttribute(lstm_recurrent_kernel, cudaFuncAttributeMaxDynamicSharedMemorySize,
                         REC_SMEM_FLOATS * (int)sizeof(float));

    const float* xl  = (const float*)d_in[0];
    const float* xr  = (const float*)d_in[1];
    const float* xo  = (const float*)d_in[2];
    const int*   yv  = (const int*)d_in[3];
    const int*   isl = (const int*)d_in[4];
    const int*   isr = (const int*)d_in[5];
    const int*   dur = (const int*)d_in[6];

    pre_gemm_kernel<<<dim3(8, TT, 2), 128, GEMM_SMEM_FLOATS * sizeof(float)>>>(
        xl, xr, xo, isl, isr,
        (const float*)d_in[7],  (const float*)d_in[9],  (const float*)d_in[10],
        (const float*)d_in[15], (const float*)d_in[17], (const float*)d_in[18]);

    lstm_recurrent_kernel<<<128, 384, REC_SMEM_FLOATS * sizeof(float)>>>(
        (const float*)d_in[8],  (const float*)d_in[16],
        (const float*)d_in[11], (const float*)d_in[12],
        (const float*)d_in[13], (const float*)d_in[14],
        (const float*)d_in[19], (const float*)d_in[20],
        (const float*)d_in[21], (const float*)d_in[22],
        dur);

    epilogue_kernel<<<1, 64>>>(
        yv,
        (const float*)d_in[23], (const float*)d_in[24],
        (const float*)d_in[25], (const float*)d_in[26],
        (const float*)d_in[27], (const float*)d_in[28],
        (float*)d_out);
}